// round 14
// baseline (speedup 1.0000x reference)
#include <cuda_runtime.h>
#include <cuda_fp16.h>
#include <stdint.h>

// Problem dims (fixed)
#define B_DIM   8
#define S_LEN   2048
#define D_DIM   1024
#define P_DIM   256
#define NQ_DIM  8192
#define M_TOT   16384
#define N_TOT   256
#define K_TOT   1024

// GEMM tiling: BM=64, BN=256 (full N), BK=32, 256 threads (8 warps 2m x 4n),
// occupancy 2 -> 256 CTAs fill all 148 SMs in one wave.
#define BM      64
#define BN      256
#define BK      32
#define KTILES  (K_TOT / BK)        // 32
#define LDA     40                  // fp16 elems per smem row (32 data + 8 pad)
#define NTHR    256

#define A_TILE_B  (BM * LDA * 2)    // 5120  (one of Ah / Al)
#define W_TILE_B  (BN * LDA * 2)    // 20480
#define ASTG_B    (2 * A_TILE_B)    // 10240  per stage (Ah + Al)
#define SM_W0     (2 * ASTG_B)      // 20480  (W: 3 stages follow)
#define SM_BIAS   (SM_W0 + 3 * W_TILE_B)   // 81920
#define SMEM_GEMM (SM_BIAS + 1024)         // 82944  (x2 CTAs = 162 KB < 228 KB)

// Device scratch (static: no allocations allowed)
__device__ __align__(16) __half g_Wt[(size_t)N_TOT * K_TOT];        // 512 KB (W^T fp16)
__device__ __align__(16) float  g_h[(size_t)M_TOT * N_TOT];         // 16 MB

// ---------------- helpers (baseline PTX only: sm_80-level) ----------------
__device__ __forceinline__ uint32_t smem_u32(const void* p) {
    uint32_t a;
    asm("{ .reg .u64 t; cvta.to.shared.u64 t, %1; cvt.u32.u64 %0, t; }" : "=r"(a) : "l"(p));
    return a;
}
__device__ __forceinline__ void cp_async16(uint32_t dst, const void* src) {
    asm volatile("cp.async.cg.shared.global [%0], [%1], 16;" :: "r"(dst), "l"(src) : "memory");
}
__device__ __forceinline__ void ldsm_x4(uint32_t* r, uint32_t addr) {
    asm volatile("ldmatrix.sync.aligned.m8n8.x4.shared.b16 {%0,%1,%2,%3}, [%4];"
                 : "=r"(r[0]), "=r"(r[1]), "=r"(r[2]), "=r"(r[3]) : "r"(addr));
}
__device__ __forceinline__ void mma16816(float* c, const uint32_t* a, uint32_t b0, uint32_t b1) {
    asm volatile(
        "mma.sync.aligned.m16n8k16.row.col.f32.f16.f16.f32 "
        "{%0,%1,%2,%3}, {%4,%5,%6,%7}, {%8,%9}, {%0,%1,%2,%3};"
        : "+f"(c[0]), "+f"(c[1]), "+f"(c[2]), "+f"(c[3])
        : "r"(a[0]), "r"(a[1]), "r"(a[2]), "r"(a[3]), "r"(b0), "r"(b1));
}
// fp16 split: hi = h_rn(x); lo = h_rn(x - hi). Packed pairs.
__device__ __forceinline__ void split2h(float x, float y, unsigned int& hw, unsigned int& lw) {
    __half hx = __float2half_rn(x);
    __half hy = __float2half_rn(y);
    __half2 hp = __halves2half2(hx, hy);
    hw = *reinterpret_cast<unsigned int*>(&hp);
    __half2 lp = __floats2half2_rn(x - __half2float(hx), y - __half2float(hy));
    lw = *reinterpret_cast<unsigned int*>(&lp);
}

// ---------------------------------------------------------------------------
// split_w: W[1024,256] fp32 -> W^T fp16 [256][1024] via smem-tiled transpose.
// 64x64 tiles: coalesced float4 reads, transpose in smem, coalesced 16B writes.
// Grid 64 blocks x 256 threads.
// ---------------------------------------------------------------------------
#define TW 64
#define TW_PAD 72    // halfs per smem row (8-half pad)
__global__ void __launch_bounds__(256)
split_w_kernel(const float* __restrict__ W) {
    __shared__ __half tile[TW][TW_PAD];   // [n][k]
    const int k0 = (blockIdx.x >> 2) * TW;        // 16 k-tiles
    const int n0 = (blockIdx.x & 3) * TW;         // 4  n-tiles
    const int t = threadIdx.x;

    // Read: 4 rows per thread, 16B coalesced, convert, transposed smem store
    const int kr = t >> 4;            // 0..15
    const int nc = (t & 15) * 4;      // 0..60
    #pragma unroll
    for (int i = 0; i < 4; i++) {
        const int k = kr + i * 16;
        float4 v = *(const float4*)(W + (size_t)(k0 + k) * N_TOT + n0 + nc);
        tile[nc + 0][k] = __float2half_rn(v.x);
        tile[nc + 1][k] = __float2half_rn(v.y);
        tile[nc + 2][k] = __float2half_rn(v.z);
        tile[nc + 3][k] = __float2half_rn(v.w);
    }
    __syncthreads();

    // Write: 2 uint4 per thread along k, fully coalesced
    const int nr = t >> 2;            // 0..63
    const int kc = (t & 3) * 8;       // 0,8,16,24
    #pragma unroll
    for (int i = 0; i < 2; i++) {
        const int k = kc + i * 32;
        *(uint4*)(g_Wt + (size_t)(n0 + nr) * K_TOT + k0 + k) =
            *(uint4*)&tile[nr][k];
    }
}

// ---------------------------------------------------------------------------
// Fused GEMM: h = A@W + bias, A split to fp16 hi/lo IN-KERNEL (2 MMA terms).
// Grid (256), 256 threads (8 warps: 2m x 4n, warp tile 32x64), occ 2.
// A: 2-stage (reg-staged LDG -> convert -> STS). W: 3-stage cp.async.
// ONE barrier per k-tile.
// ---------------------------------------------------------------------------
__global__ void __launch_bounds__(NTHR, 2)
gemm_fused_kernel(const float* __restrict__ A, const float* __restrict__ bias) {
    extern __shared__ char smem[];
    const uint32_t sb = smem_u32(smem);
    const int tid  = threadIdx.x;
    const int lane = tid & 31;
    const int wid  = tid >> 5;
    const int m0 = blockIdx.x * BM;
    const int mw = (wid >> 2) * 32;   // warp m offset (2 m-warps)
    const int nw = (wid & 3) * 64;    // warp n offset (4 n-warps)

    float* bias_s = (float*)(smem + SM_BIAS);
    if (tid < BN) bias_s[tid] = bias[tid];

    float acc[2][8][4];
    #pragma unroll
    for (int i = 0; i < 2; i++)
        #pragma unroll
        for (int j = 0; j < 8; j++)
            #pragma unroll
            for (int v = 0; v < 4; v++) acc[i][j][v] = 0.f;

    // ---- W stage issue (cp.async): 256 rows x 32 k fp16, 4 granules/thread ----
    auto issue_w = [&](int slot3, int kt) {
        const uint32_t wst = sb + SM_W0 + slot3 * W_TILE_B;
        const int k0 = kt * BK;
        #pragma unroll
        for (int it = 0; it < 4; it++) {
            const int idx = (it << 8) + tid;          // 0..1023
            const int row = idx >> 2, g = idx & 3;
            uint32_t dst = wst + (uint32_t)(row * LDA + g * 8) * 2;
            cp_async16(dst, g_Wt + (size_t)row * K_TOT + k0 + g * 8);
        }
        asm volatile("cp.async.commit_group;" ::: "memory");
    };

    // A register prefetch + in-kernel fp16 split/store. 8 floats/thread:
    // row = tid>>2 (0..63), k-quarter = (tid&3)*8.
    const int arow = tid >> 2;
    const int akq  = (tid & 3) * 8;
    const float* abase = A + (size_t)(m0 + arow) * K_TOT + akq;
    float4 pv[2];
    auto ldgA = [&](int kt) {
        const float* s = abase + kt * BK;
        pv[0] = *(const float4*)(s + 0);
        pv[1] = *(const float4*)(s + 4);
    };
    auto stsA = [&](int slot2) {
        const uint32_t astg_off = slot2 * ASTG_B;
        unsigned int hw[4], lw[4];
        const float* f = (const float*)pv;
        #pragma unroll
        for (int p = 0; p < 4; p++) split2h(f[2*p], f[2*p+1], hw[p], lw[p]);
        const uint32_t off = (uint32_t)(arow * LDA + akq) * 2;
        *(uint4*)(smem + astg_off + off)             = make_uint4(hw[0], hw[1], hw[2], hw[3]);
        *(uint4*)(smem + astg_off + A_TILE_B + off)  = make_uint4(lw[0], lw[1], lw[2], lw[3]);
    };

    const uint32_t a_row = lane & 15;
    const uint32_t a_g   = lane >> 4;

    auto compute = [&](int slot2, int slot3) {
        const uint32_t astg = sb + slot2 * ASTG_B;
        const uint32_t wst  = sb + SM_W0 + slot3 * W_TILE_B;
        #pragma unroll
        for (int k16 = 0; k16 < 2; k16++) {
            const uint32_t aoff = (uint32_t)((mw + a_row) * LDA + k16 * 16 + a_g * 8) * 2;
            uint32_t ah0[4], ah1[4], al0[4], al1[4];
            ldsm_x4(ah0, astg + aoff);
            ldsm_x4(ah1, astg + aoff + 16 * LDA * 2);
            ldsm_x4(al0, astg + A_TILE_B + aoff);
            ldsm_x4(al1, astg + A_TILE_B + aoff + 16 * LDA * 2);

            // W frags double-buffered in regs: LDSM one nq ahead of its MMAs
            uint32_t wa[4], wb[4];
            auto woff = [&](int nq) {
                return (uint32_t)((nw + nq * 16 + a_row) * LDA + k16 * 16 + a_g * 8) * 2;
            };
            ldsm_x4(wa, wst + woff(0));
            #pragma unroll
            for (int nq = 0; nq < 4; nq++) {
                uint32_t* wc = (nq & 1) ? wb : wa;
                uint32_t* wn = (nq & 1) ? wa : wb;
                if (nq < 3) ldsm_x4(wn, wst + woff(nq + 1));
                mma16816(acc[0][2*nq],   ah0, wc[0], wc[2]);
                mma16816(acc[0][2*nq+1], ah0, wc[1], wc[3]);
                mma16816(acc[1][2*nq],   ah1, wc[0], wc[2]);
                mma16816(acc[1][2*nq+1], ah1, wc[1], wc[3]);
                mma16816(acc[0][2*nq],   al0, wc[0], wc[2]);   // Al @ W
                mma16816(acc[0][2*nq+1], al0, wc[1], wc[3]);
                mma16816(acc[1][2*nq],   al1, wc[0], wc[2]);
                mma16816(acc[1][2*nq+1], al1, wc[1], wc[3]);
            }
        }
    };

    // ---- prologue: stage A(0), A(1) regs, W(0), W(1) ----
    ldgA(0);
    issue_w(0, 0);
    issue_w(1, 1);
    stsA(0);                  // consumes LDG(0)
    ldgA(1);
    asm volatile("cp.async.wait_group 1;" ::: "memory");  // W(0) done
    __syncthreads();

    // ---- mainloop: ONE barrier per kt (W 3-stage -> reuse distance 2) ----
    for (int kt = 0; kt < KTILES; kt++) {
        compute(kt & 1, kt % 3);
        if (kt + 1 < KTILES) {
            stsA((kt + 1) & 1);           // regs hold A(kt+1)
            if (kt + 2 < KTILES) {
                ldgA(kt + 2);
                issue_w((kt + 2) % 3, kt + 2);
                asm volatile("cp.async.wait_group 1;" ::: "memory");  // W(kt+1) done
            } else {
                asm volatile("cp.async.wait_group 0;" ::: "memory");
            }
            __syncthreads();
        }
    }

    // ---- epilogue: bias + store fp32 h ----
    const int crow = lane >> 2;        // 0..7
    const int ccol = (lane & 3) * 2;   // 0,2,4,6
    #pragma unroll
    for (int mt = 0; mt < 2; mt++) {
        const int mrow = m0 + mw + mt * 16 + crow;
        #pragma unroll
        for (int nt = 0; nt < 8; nt++) {
            const int nc = nw + nt * 8 + ccol;
            const float b0 = bias_s[nc], b1 = bias_s[nc + 1];
            float2 v0 = make_float2(acc[mt][nt][0] + b0, acc[mt][nt][1] + b1);
            float2 v1 = make_float2(acc[mt][nt][2] + b0, acc[mt][nt][3] + b1);
            *(float2*)&g_h[(size_t)mrow * N_TOT + nc] = v0;
            *(float2*)&g_h[(size_t)(mrow + 8) * N_TOT + nc] = v1;
        }
    }
}

// ---------------------------------------------------------------------------
// Gather: 4 q per 256-thread block; each thread does 4 independent float4
// loads (s/e x set1/set2) + 4 coalesced stores. MLP = 4.
// ---------------------------------------------------------------------------
__global__ void __launch_bounds__(256)
gather_kernel(const int* __restrict__ qb,
              const int* __restrict__ s1, const int* __restrict__ e1,
              const int* __restrict__ s2, const int* __restrict__ e2,
              float* __restrict__ out) {
    const int q  = blockIdx.x * 4 + (threadIdx.x >> 6);
    const int th = threadIdx.x & 63;          // 64 threads per q
    const int col = th * 4;                   // float4 col within 256
    const int b = __ldg(&qb[q]);
    const int sA = __ldg(&s1[q]), eA = __ldg(&e1[q]);
    const int sB = __ldg(&s2[q]), eB = __ldg(&e2[q]);
    const size_t brow = (size_t)b * S_LEN;

    float4 z = make_float4(0.f, 0.f, 0.f, 0.f);
    float4 vs1 = z, ve1 = z, vs2 = z, ve2 = z;
    if (eA >= sA) {
        vs1 = *(const float4*)&g_h[(brow + sA) * N_TOT + col];
        ve1 = *(const float4*)&g_h[(brow + eA) * N_TOT + col];
    }
    if (eB >= sB) {
        vs2 = *(const float4*)&g_h[(brow + sB) * N_TOT + col];
        ve2 = *(const float4*)&g_h[(brow + eB) * N_TOT + col];
    }
    float* o1 = out + (size_t)q * (2 * P_DIM);
    float* o2 = out + ((size_t)NQ_DIM + q) * (2 * P_DIM);
    *(float4*)(o1 + col)          = vs1;
    *(float4*)(o1 + P_DIM + col)  = ve1;
    *(float4*)(o2 + col)          = vs2;
    *(float4*)(o2 + P_DIM + col)  = ve2;
}

// ---------------------------------------------------------------------------
// Inputs: flag, encoded_input, start_ids_1, end_ids_1, query_batch_idx,
// start_ids_2, end_ids_2, W, b. Output: res1 then res2, each [NQ, 512] fp32.
// ---------------------------------------------------------------------------
extern "C" void kernel_launch(void* const* d_in, const int* in_sizes, int n_in,
                              void* d_out, int out_size) {
    const float* enc  = (const float*)d_in[1];
    const int*   s1   = (const int*)d_in[2];
    const int*   e1   = (const int*)d_in[3];
    const int*   qb   = (const int*)d_in[4];
    const int*   s2   = (const int*)d_in[5];
    const int*   e2   = (const int*)d_in[6];
    const float* W    = (const float*)d_in[7];
    const float* bias = (const float*)d_in[8];
    float* out = (float*)d_out;

    cudaFuncSetAttribute(gemm_fused_kernel,
                         cudaFuncAttributeMaxDynamicSharedMemorySize, SMEM_GEMM);

    split_w_kernel<<<(K_TOT / TW) * (N_TOT / TW), 256>>>(W);     // 64 blocks
    gemm_fused_kernel<<<M_TOT / BM, NTHR, SMEM_GEMM>>>(enc, bias);
    gather_kernel<<<NQ_DIM / 4, 256>>>(qb, s1, e1, s2, e2, out);
}

// round 15
// speedup vs baseline: 1.4916x; 1.4916x over previous
#include <cuda_runtime.h>
#include <cuda_fp16.h>
#include <stdint.h>

// Problem dims (fixed)
#define B_DIM   8
#define S_LEN   2048
#define D_DIM   1024
#define P_DIM   256
#define NQ_DIM  8192
#define M_TOT   16384
#define N_TOT   256
#define K_TOT   1024

// GEMM tiling: BM=128, BN=256 (full N), BK=32, 512 threads (16 warps 4m x 4n)
#define BM      128
#define BN      256
#define BK      32
#define KTILES  (K_TOT / BK)        // 32
#define LDA     40                  // fp16 elems per smem row (32 data + 8 pad)
#define NTHR    512

#define A_TILE_B  (BM * LDA * 2)    // 10240  (one of Ah / Al)
#define W_TILE_B  (BN * LDA * 2)    // 20480
#define ASTG_B    (2 * A_TILE_B)    // 20480  per stage (Ah + Al)
#define SM_W0     (2 * ASTG_B)      // 40960  (W: 3 stages follow)
#define SM_BIAS   (SM_W0 + 3 * W_TILE_B)   // 102400
#define SMEM_GEMM (SM_BIAS + 1024)         // 103424

// Device scratch (static: no allocations allowed)
__device__ __align__(16) __half g_Wt[(size_t)N_TOT * K_TOT];        // 512 KB (W^T fp16)
__device__ __align__(16) float  g_h[(size_t)M_TOT * N_TOT];         // 16 MB

// ---------------- helpers (baseline PTX only: sm_80-level) ----------------
__device__ __forceinline__ uint32_t smem_u32(const void* p) {
    uint32_t a;
    asm("{ .reg .u64 t; cvta.to.shared.u64 t, %1; cvt.u32.u64 %0, t; }" : "=r"(a) : "l"(p));
    return a;
}
__device__ __forceinline__ void cp_async16(uint32_t dst, const void* src) {
    asm volatile("cp.async.cg.shared.global [%0], [%1], 16;" :: "r"(dst), "l"(src) : "memory");
}
__device__ __forceinline__ void ldsm_x4(uint32_t* r, uint32_t addr) {
    asm volatile("ldmatrix.sync.aligned.m8n8.x4.shared.b16 {%0,%1,%2,%3}, [%4];"
                 : "=r"(r[0]), "=r"(r[1]), "=r"(r[2]), "=r"(r[3]) : "r"(addr));
}
__device__ __forceinline__ void mma16816(float* c, const uint32_t* a, uint32_t b0, uint32_t b1) {
    asm volatile(
        "mma.sync.aligned.m16n8k16.row.col.f32.f16.f16.f32 "
        "{%0,%1,%2,%3}, {%4,%5,%6,%7}, {%8,%9}, {%0,%1,%2,%3};"
        : "+f"(c[0]), "+f"(c[1]), "+f"(c[2]), "+f"(c[3])
        : "r"(a[0]), "r"(a[1]), "r"(a[2]), "r"(a[3]), "r"(b0), "r"(b1));
}
// fp16 split: hi = h_rn(x); lo = h_rn(x - hi). Packed pairs.
__device__ __forceinline__ void split2h(float x, float y, unsigned int& hw, unsigned int& lw) {
    __half hx = __float2half_rn(x);
    __half hy = __float2half_rn(y);
    __half2 hp = __halves2half2(hx, hy);
    hw = *reinterpret_cast<unsigned int*>(&hp);
    __half2 lp = __floats2half2_rn(x - __half2float(hx), y - __half2float(hy));
    lw = *reinterpret_cast<unsigned int*>(&lp);
}

// ---------------------------------------------------------------------------
// split_w: W[1024,256] fp32 -> W^T fp16 [256][1024] (k-contiguous).
// R12 variant (best measured). 4 elems/thread, 256 blocks.
// ---------------------------------------------------------------------------
__global__ void __launch_bounds__(256)
split_w_kernel(const float* __restrict__ W) {
    int t = blockIdx.x * 256 + threadIdx.x;   // 0 .. 65535
    int n  = t >> 8;
    int k4 = t & 255;
    unsigned int hw[2];
    #pragma unroll
    for (int p = 0; p < 2; p++) {
        float x = W[(size_t)(k4 * 4 + 2 * p)     * N_TOT + n];
        float y = W[(size_t)(k4 * 4 + 2 * p + 1) * N_TOT + n];
        __half2 hp = __floats2half2_rn(x, y);
        hw[p] = *reinterpret_cast<unsigned int*>(&hp);
    }
    *(uint2*)(g_Wt + (size_t)n * K_TOT + k4 * 4) = make_uint2(hw[0], hw[1]);
}

// ---------------------------------------------------------------------------
// Fused GEMM: h = A@W + bias, A split to fp16 hi/lo IN-KERNEL (2 MMA terms).
// Grid (128), 512 threads (16 warps: 4m x 4n, warp tile 32x64).
// A: 2-stage (reg-staged LDG -> convert -> STS). W: 3-stage cp.async.
// ONE barrier per k-tile; all producer work hoisted BEFORE compute so the
// HMMA stream hides LDG/cvt/STS latency.
// ---------------------------------------------------------------------------
__global__ void __launch_bounds__(NTHR, 1)
gemm_fused_kernel(const float* __restrict__ A, const float* __restrict__ bias) {
    extern __shared__ char smem[];
    const uint32_t sb = smem_u32(smem);
    const int tid  = threadIdx.x;
    const int lane = tid & 31;
    const int wid  = tid >> 5;
    const int m0 = blockIdx.x * BM;
    const int mw = (wid >> 2) * 32;   // warp m offset
    const int nw = (wid & 3) * 64;    // warp n offset

    float* bias_s = (float*)(smem + SM_BIAS);
    if (tid < BN) bias_s[tid] = bias[tid];

    float acc[2][8][4];
    #pragma unroll
    for (int i = 0; i < 2; i++)
        #pragma unroll
        for (int j = 0; j < 8; j++)
            #pragma unroll
            for (int v = 0; v < 4; v++) acc[i][j][v] = 0.f;

    // ---- W stage issue (cp.async): 256 rows x 32 k fp16, 2 granules/thread ----
    auto issue_w = [&](int slot3, int kt) {
        const uint32_t wst = sb + SM_W0 + slot3 * W_TILE_B;
        const int k0 = kt * BK;
        #pragma unroll
        for (int it = 0; it < 2; it++) {
            const int idx = (it << 9) + tid;          // 0..1023
            const int row = idx >> 2, g = idx & 3;
            uint32_t dst = wst + (uint32_t)(row * LDA + g * 8) * 2;
            cp_async16(dst, g_Wt + (size_t)row * K_TOT + k0 + g * 8);
        }
        asm volatile("cp.async.commit_group;" ::: "memory");
    };

    // A register prefetch + in-kernel fp16 split/store. 8 floats/thread:
    // row = tid>>2 (0..127), k-quarter = (tid&3)*8.
    const int arow = tid >> 2;
    const int akq  = (tid & 3) * 8;
    const float* abase = A + (size_t)(m0 + arow) * K_TOT + akq;
    float4 pv[2];
    auto ldgA = [&](int kt) {
        const float* s = abase + kt * BK;
        pv[0] = *(const float4*)(s + 0);
        pv[1] = *(const float4*)(s + 4);
    };
    auto stsA = [&](int slot2) {
        const uint32_t astg_off = slot2 * ASTG_B;
        unsigned int hw[4], lw[4];
        const float* f = (const float*)pv;
        #pragma unroll
        for (int p = 0; p < 4; p++) split2h(f[2*p], f[2*p+1], hw[p], lw[p]);
        const uint32_t off = (uint32_t)(arow * LDA + akq) * 2;
        *(uint4*)(smem + astg_off + off)             = make_uint4(hw[0], hw[1], hw[2], hw[3]);
        *(uint4*)(smem + astg_off + A_TILE_B + off)  = make_uint4(lw[0], lw[1], lw[2], lw[3]);
    };

    const uint32_t a_row = lane & 15;
    const uint32_t a_g   = lane >> 4;

    auto compute = [&](int slot2, int slot3) {
        const uint32_t astg = sb + slot2 * ASTG_B;
        const uint32_t wst  = sb + SM_W0 + slot3 * W_TILE_B;
        #pragma unroll
        for (int k16 = 0; k16 < 2; k16++) {
            const uint32_t aoff = (uint32_t)((mw + a_row) * LDA + k16 * 16 + a_g * 8) * 2;
            uint32_t ah0[4], ah1[4], al0[4], al1[4];
            ldsm_x4(ah0, astg + aoff);
            ldsm_x4(ah1, astg + aoff + 16 * LDA * 2);
            ldsm_x4(al0, astg + A_TILE_B + aoff);
            ldsm_x4(al1, astg + A_TILE_B + aoff + 16 * LDA * 2);

            // W frags double-buffered in regs: LDSM one nq ahead of its MMAs
            uint32_t wa[4], wb[4];
            auto woff = [&](int nq) {
                return (uint32_t)((nw + nq * 16 + a_row) * LDA + k16 * 16 + a_g * 8) * 2;
            };
            ldsm_x4(wa, wst + woff(0));
            #pragma unroll
            for (int nq = 0; nq < 4; nq++) {
                uint32_t* wc = (nq & 1) ? wb : wa;
                uint32_t* wn = (nq & 1) ? wa : wb;
                if (nq < 3) ldsm_x4(wn, wst + woff(nq + 1));
                mma16816(acc[0][2*nq],   ah0, wc[0], wc[2]);
                mma16816(acc[0][2*nq+1], ah0, wc[1], wc[3]);
                mma16816(acc[1][2*nq],   ah1, wc[0], wc[2]);
                mma16816(acc[1][2*nq+1], ah1, wc[1], wc[3]);
                mma16816(acc[0][2*nq],   al0, wc[0], wc[2]);   // Al @ W
                mma16816(acc[0][2*nq+1], al0, wc[1], wc[3]);
                mma16816(acc[1][2*nq],   al1, wc[0], wc[2]);
                mma16816(acc[1][2*nq+1], al1, wc[1], wc[3]);
            }
        }
    };

    // ---- prologue: stage A(0), A(1) regs, W(0), W(1) ----
    ldgA(0);
    issue_w(0, 0);
    issue_w(1, 1);
    stsA(0);                  // consumes LDG(0)
    ldgA(1);
    asm volatile("cp.async.wait_group 1;" ::: "memory");  // W(0) done
    __syncthreads();

    // ---- mainloop: producers FIRST (hidden under compute), ONE barrier/kt ----
    for (int kt = 0; kt < KTILES; kt++) {
        if (kt + 1 < KTILES) {
            stsA((kt + 1) & 1);               // pv holds A(kt+1); other A slot
            if (kt + 2 < KTILES) {
                ldgA(kt + 2);                 // refill pv
                issue_w((kt + 2) % 3, kt + 2);
            }
        }
        compute(kt & 1, kt % 3);
        if (kt + 1 < KTILES) {
            if (kt + 2 < KTILES)
                asm volatile("cp.async.wait_group 1;" ::: "memory");  // W(kt+1) done
            else
                asm volatile("cp.async.wait_group 0;" ::: "memory");
            __syncthreads();
        }
    }

    // ---- epilogue: bias + store fp32 h ----
    const int crow = lane >> 2;        // 0..7
    const int ccol = (lane & 3) * 2;   // 0,2,4,6
    #pragma unroll
    for (int mt = 0; mt < 2; mt++) {
        const int mrow = m0 + mw + mt * 16 + crow;
        #pragma unroll
        for (int nt = 0; nt < 8; nt++) {
            const int nc = nw + nt * 8 + ccol;
            const float b0 = bias_s[nc], b1 = bias_s[nc + 1];
            float2 v0 = make_float2(acc[mt][nt][0] + b0, acc[mt][nt][1] + b1);
            float2 v1 = make_float2(acc[mt][nt][2] + b0, acc[mt][nt][3] + b1);
            *(float2*)&g_h[(size_t)mrow * N_TOT + nc] = v0;
            *(float2*)&g_h[(size_t)(mrow + 8) * N_TOT + nc] = v1;
        }
    }
}

// ---------------------------------------------------------------------------
// Gather: 8 q per 512-thread block; each thread does 4 independent float4
// loads (s/e x set1/set2) + 4 coalesced stores. More warps -> more MLP/SM.
// ---------------------------------------------------------------------------
__global__ void __launch_bounds__(512)
gather_kernel(const int* __restrict__ qb,
              const int* __restrict__ s1, const int* __restrict__ e1,
              const int* __restrict__ s2, const int* __restrict__ e2,
              float* __restrict__ out) {
    const int q  = blockIdx.x * 8 + (threadIdx.x >> 6);
    const int th = threadIdx.x & 63;          // 64 threads per q
    const int col = th * 4;                   // float4 col within 256
    const int b = __ldg(&qb[q]);
    const int sA = __ldg(&s1[q]), eA = __ldg(&e1[q]);
    const int sB = __ldg(&s2[q]), eB = __ldg(&e2[q]);
    const size_t brow = (size_t)b * S_LEN;

    float4 z = make_float4(0.f, 0.f, 0.f, 0.f);
    float4 vs1 = z, ve1 = z, vs2 = z, ve2 = z;
    if (eA >= sA) {
        vs1 = *(const float4*)&g_h[(brow + sA) * N_TOT + col];
        ve1 = *(const float4*)&g_h[(brow + eA) * N_TOT + col];
    }
    if (eB >= sB) {
        vs2 = *(const float4*)&g_h[(brow + sB) * N_TOT + col];
        ve2 = *(const float4*)&g_h[(brow + eB) * N_TOT + col];
    }
    float* o1 = out + (size_t)q * (2 * P_DIM);
    float* o2 = out + ((size_t)NQ_DIM + q) * (2 * P_DIM);
    *(float4*)(o1 + col)          = vs1;
    *(float4*)(o1 + P_DIM + col)  = ve1;
    *(float4*)(o2 + col)          = vs2;
    *(float4*)(o2 + P_DIM + col)  = ve2;
}

// ---------------------------------------------------------------------------
// Inputs: flag, encoded_input, start_ids_1, end_ids_1, query_batch_idx,
// start_ids_2, end_ids_2, W, b. Output: res1 then res2, each [NQ, 512] fp32.
// ---------------------------------------------------------------------------
extern "C" void kernel_launch(void* const* d_in, const int* in_sizes, int n_in,
                              void* d_out, int out_size) {
    const float* enc  = (const float*)d_in[1];
    const int*   s1   = (const int*)d_in[2];
    const int*   e1   = (const int*)d_in[3];
    const int*   qb   = (const int*)d_in[4];
    const int*   s2   = (const int*)d_in[5];
    const int*   e2   = (const int*)d_in[6];
    const float* W    = (const float*)d_in[7];
    const float* bias = (const float*)d_in[8];
    float* out = (float*)d_out;

    cudaFuncSetAttribute(gemm_fused_kernel,
                         cudaFuncAttributeMaxDynamicSharedMemorySize, SMEM_GEMM);

    split_w_kernel<<<N_TOT * (K_TOT / 4) / 256, 256>>>(W);       // 256 blocks
    gemm_fused_kernel<<<M_TOT / BM, NTHR, SMEM_GEMM>>>(enc, bias);
    gather_kernel<<<NQ_DIM / 8, 512>>>(qb, s1, e1, s2, e2, out);
}

// round 16
// speedup vs baseline: 1.5285x; 1.0247x over previous
#include <cuda_runtime.h>
#include <cuda_fp16.h>
#include <stdint.h>

// Problem dims (fixed)
#define B_DIM   8
#define S_LEN   2048
#define D_DIM   1024
#define P_DIM   256
#define NQ_DIM  8192
#define M_TOT   16384
#define N_TOT   256
#define K_TOT   1024

// GEMM tiling: BM=128, BN=256 (full N), BK=64, 512 threads (16 warps 4m x 4n)
#define BM      128
#define BN      256
#define BK      64
#define KTILES  (K_TOT / BK)        // 16
#define LDA     72                  // fp16 elems per smem row (64 data + 8 pad)
#define NTHR    512

#define A_TILE_B  (BM * LDA * 2)    // 18432  (one of Ah / Al)
#define W_TILE_B  (BN * LDA * 2)    // 36864
#define ASTG_B    (2 * A_TILE_B)    // 36864  per stage (Ah + Al)
#define SM_W0     (2 * ASTG_B)      // 73728  (W: 3 stages follow)
#define SM_BIAS   (SM_W0 + 3 * W_TILE_B)   // 184320
#define SMEM_GEMM (SM_BIAS + 1024)         // 185344

// Device scratch (static: no allocations allowed)
__device__ __align__(16) __half g_Wt[(size_t)N_TOT * K_TOT];        // 512 KB (W^T fp16)
__device__ __align__(16) float  g_h[(size_t)M_TOT * N_TOT];         // 16 MB

// ---------------- helpers (baseline PTX only: sm_80-level) ----------------
__device__ __forceinline__ uint32_t smem_u32(const void* p) {
    uint32_t a;
    asm("{ .reg .u64 t; cvta.to.shared.u64 t, %1; cvt.u32.u64 %0, t; }" : "=r"(a) : "l"(p));
    return a;
}
__device__ __forceinline__ void cp_async16(uint32_t dst, const void* src) {
    asm volatile("cp.async.cg.shared.global [%0], [%1], 16;" :: "r"(dst), "l"(src) : "memory");
}
__device__ __forceinline__ void ldsm_x4(uint32_t* r, uint32_t addr) {
    asm volatile("ldmatrix.sync.aligned.m8n8.x4.shared.b16 {%0,%1,%2,%3}, [%4];"
                 : "=r"(r[0]), "=r"(r[1]), "=r"(r[2]), "=r"(r[3]) : "r"(addr));
}
__device__ __forceinline__ void mma16816(float* c, const uint32_t* a, uint32_t b0, uint32_t b1) {
    asm volatile(
        "mma.sync.aligned.m16n8k16.row.col.f32.f16.f16.f32 "
        "{%0,%1,%2,%3}, {%4,%5,%6,%7}, {%8,%9}, {%0,%1,%2,%3};"
        : "+f"(c[0]), "+f"(c[1]), "+f"(c[2]), "+f"(c[3])
        : "r"(a[0]), "r"(a[1]), "r"(a[2]), "r"(a[3]), "r"(b0), "r"(b1));
}
// fp16 split: hi = h_rn(x); lo = h_rn(x - hi). Packed pairs.
__device__ __forceinline__ void split2h(float x, float y, unsigned int& hw, unsigned int& lw) {
    __half hx = __float2half_rn(x);
    __half hy = __float2half_rn(y);
    __half2 hp = __halves2half2(hx, hy);
    hw = *reinterpret_cast<unsigned int*>(&hp);
    __half2 lp = __floats2half2_rn(x - __half2float(hx), y - __half2float(hy));
    lw = *reinterpret_cast<unsigned int*>(&lp);
}

// ---------------------------------------------------------------------------
// split_w: W[1024,256] fp32 -> W^T fp16 [256][1024]. COALESCED READS:
// block handles 4 consecutive k-rows; thread tid = n. 4 independent row
// loads (MLP 4), convert, one 8B scattered store (fire-and-forget).
// Grid 256 blocks x 256 threads.
// ---------------------------------------------------------------------------
__global__ void __launch_bounds__(256)
split_w_kernel(const float* __restrict__ W) {
    const int k0 = blockIdx.x * 4;
    const int n  = threadIdx.x;
    float v0 = W[(size_t)(k0 + 0) * N_TOT + n];
    float v1 = W[(size_t)(k0 + 1) * N_TOT + n];
    float v2 = W[(size_t)(k0 + 2) * N_TOT + n];
    float v3 = W[(size_t)(k0 + 3) * N_TOT + n];
    __half2 p0 = __floats2half2_rn(v0, v1);
    __half2 p1 = __floats2half2_rn(v2, v3);
    uint2 pk;
    pk.x = *reinterpret_cast<unsigned int*>(&p0);
    pk.y = *reinterpret_cast<unsigned int*>(&p1);
    *(uint2*)(g_Wt + (size_t)n * K_TOT + k0) = pk;
}

// ---------------------------------------------------------------------------
// Fused GEMM: h = A@W + bias, A split to fp16 hi/lo IN-KERNEL (2 MMA terms).
// Grid (128), 512 threads (16 warps: 4m x 4n, warp tile 32x64). BK=64 ->
// 16 k-tiles, ONE barrier each. A: 2-stage (reg LDG -> cvt -> STS).
// W: 3-stage cp.async. R13 ordering: compute FIRST, then producers.
// ---------------------------------------------------------------------------
__global__ void __launch_bounds__(NTHR, 1)
gemm_fused_kernel(const float* __restrict__ A, const float* __restrict__ bias) {
    extern __shared__ char smem[];
    const uint32_t sb = smem_u32(smem);
    const int tid  = threadIdx.x;
    const int lane = tid & 31;
    const int wid  = tid >> 5;
    const int m0 = blockIdx.x * BM;
    const int mw = (wid >> 2) * 32;   // warp m offset
    const int nw = (wid & 3) * 64;    // warp n offset

    float* bias_s = (float*)(smem + SM_BIAS);
    if (tid < BN) bias_s[tid] = bias[tid];

    float acc[2][8][4];
    #pragma unroll
    for (int i = 0; i < 2; i++)
        #pragma unroll
        for (int j = 0; j < 8; j++)
            #pragma unroll
            for (int v = 0; v < 4; v++) acc[i][j][v] = 0.f;

    // ---- W stage issue (cp.async): 256 rows x 64 k fp16, 4 granules/thread ----
    auto issue_w = [&](int slot3, int kt) {
        const uint32_t wst = sb + SM_W0 + slot3 * W_TILE_B;
        const int k0 = kt * BK;
        #pragma unroll
        for (int it = 0; it < 4; it++) {
            const int idx = (it << 9) + tid;          // 0..2047
            const int row = idx >> 3, g = idx & 7;
            uint32_t dst = wst + (uint32_t)(row * LDA + g * 8) * 2;
            cp_async16(dst, g_Wt + (size_t)row * K_TOT + k0 + g * 8);
        }
        asm volatile("cp.async.commit_group;" ::: "memory");
    };

    // A register prefetch + in-kernel fp16 split/store. 16 floats/thread:
    // row = tid>>2 (0..127), k-quarter = (tid&3)*16.
    const int arow = tid >> 2;
    const int akq  = (tid & 3) * 16;
    const float* abase = A + (size_t)(m0 + arow) * K_TOT + akq;
    float4 pv[4];
    auto ldgA = [&](int kt) {
        const float* s = abase + kt * BK;
        pv[0] = *(const float4*)(s + 0);
        pv[1] = *(const float4*)(s + 4);
        pv[2] = *(const float4*)(s + 8);
        pv[3] = *(const float4*)(s + 12);
    };
    auto stsA = [&](int slot2) {
        const uint32_t astg_off = slot2 * ASTG_B;
        unsigned int hw[8], lw[8];
        const float* f = (const float*)pv;
        #pragma unroll
        for (int p = 0; p < 8; p++) split2h(f[2*p], f[2*p+1], hw[p], lw[p]);
        const uint32_t off = (uint32_t)(arow * LDA + akq) * 2;
        *(uint4*)(smem + astg_off + off)      = make_uint4(hw[0], hw[1], hw[2], hw[3]);
        *(uint4*)(smem + astg_off + off + 16) = make_uint4(hw[4], hw[5], hw[6], hw[7]);
        *(uint4*)(smem + astg_off + A_TILE_B + off)      = make_uint4(lw[0], lw[1], lw[2], lw[3]);
        *(uint4*)(smem + astg_off + A_TILE_B + off + 16) = make_uint4(lw[4], lw[5], lw[6], lw[7]);
    };

    const uint32_t a_row = lane & 15;
    const uint32_t a_g   = lane >> 4;

    auto compute = [&](int slot2, int slot3) {
        const uint32_t astg = sb + slot2 * ASTG_B;
        const uint32_t wst  = sb + SM_W0 + slot3 * W_TILE_B;
        #pragma unroll
        for (int k16 = 0; k16 < 4; k16++) {
            const uint32_t aoff = (uint32_t)((mw + a_row) * LDA + k16 * 16 + a_g * 8) * 2;
            uint32_t ah0[4], ah1[4], al0[4], al1[4];
            ldsm_x4(ah0, astg + aoff);
            ldsm_x4(ah1, astg + aoff + 16 * LDA * 2);
            ldsm_x4(al0, astg + A_TILE_B + aoff);
            ldsm_x4(al1, astg + A_TILE_B + aoff + 16 * LDA * 2);

            // W frags double-buffered in regs: LDSM one nq ahead of its MMAs
            uint32_t wa[4], wb[4];
            auto woff = [&](int nq) {
                return (uint32_t)((nw + nq * 16 + a_row) * LDA + k16 * 16 + a_g * 8) * 2;
            };
            ldsm_x4(wa, wst + woff(0));
            #pragma unroll
            for (int nq = 0; nq < 4; nq++) {
                uint32_t* wc = (nq & 1) ? wb : wa;
                uint32_t* wn = (nq & 1) ? wa : wb;
                if (nq < 3) ldsm_x4(wn, wst + woff(nq + 1));
                mma16816(acc[0][2*nq],   ah0, wc[0], wc[2]);
                mma16816(acc[0][2*nq+1], ah0, wc[1], wc[3]);
                mma16816(acc[1][2*nq],   ah1, wc[0], wc[2]);
                mma16816(acc[1][2*nq+1], ah1, wc[1], wc[3]);
                mma16816(acc[0][2*nq],   al0, wc[0], wc[2]);   // Al @ W
                mma16816(acc[0][2*nq+1], al0, wc[1], wc[3]);
                mma16816(acc[1][2*nq],   al1, wc[0], wc[2]);
                mma16816(acc[1][2*nq+1], al1, wc[1], wc[3]);
            }
        }
    };

    // ---- prologue: stage A(0), A(1) regs, W(0), W(1) ----
    ldgA(0);
    issue_w(0, 0);
    issue_w(1, 1);
    stsA(0);                  // consumes LDG(0)
    ldgA(1);
    asm volatile("cp.async.wait_group 1;" ::: "memory");  // W(0) done
    __syncthreads();

    // ---- mainloop: compute FIRST (R13 ordering), ONE barrier per kt ----
    for (int kt = 0; kt < KTILES; kt++) {
        compute(kt & 1, kt % 3);
        if (kt + 1 < KTILES) {
            stsA((kt + 1) & 1);           // regs hold A(kt+1)
            if (kt + 2 < KTILES) {
                ldgA(kt + 2);
                issue_w((kt + 2) % 3, kt + 2);
                asm volatile("cp.async.wait_group 1;" ::: "memory");  // W(kt+1) done
            } else {
                asm volatile("cp.async.wait_group 0;" ::: "memory");
            }
            __syncthreads();
        }
    }

    // ---- epilogue: bias + store fp32 h ----
    const int crow = lane >> 2;        // 0..7
    const int ccol = (lane & 3) * 2;   // 0,2,4,6
    #pragma unroll
    for (int mt = 0; mt < 2; mt++) {
        const int mrow = m0 + mw + mt * 16 + crow;
        #pragma unroll
        for (int nt = 0; nt < 8; nt++) {
            const int nc = nw + nt * 8 + ccol;
            const float b0 = bias_s[nc], b1 = bias_s[nc + 1];
            float2 v0 = make_float2(acc[mt][nt][0] + b0, acc[mt][nt][1] + b1);
            float2 v1 = make_float2(acc[mt][nt][2] + b0, acc[mt][nt][3] + b1);
            *(float2*)&g_h[(size_t)mrow * N_TOT + nc] = v0;
            *(float2*)&g_h[(size_t)(mrow + 8) * N_TOT + nc] = v1;
        }
    }
}

// ---------------------------------------------------------------------------
// Gather (R13 version): 4 q per 256-thread block; each thread 4 independent
// float4 loads (s/e x set1/set2) + 4 coalesced stores. MLP = 4.
// ---------------------------------------------------------------------------
__global__ void __launch_bounds__(256)
gather_kernel(const int* __restrict__ qb,
              const int* __restrict__ s1, const int* __restrict__ e1,
              const int* __restrict__ s2, const int* __restrict__ e2,
              float* __restrict__ out) {
    const int q  = blockIdx.x * 4 + (threadIdx.x >> 6);
    const int th = threadIdx.x & 63;          // 64 threads per q
    const int col = th * 4;                   // float4 col within 256
    const int b = __ldg(&qb[q]);
    const int sA = __ldg(&s1[q]), eA = __ldg(&e1[q]);
    const int sB = __ldg(&s2[q]), eB = __ldg(&e2[q]);
    const size_t brow = (size_t)b * S_LEN;

    float4 z = make_float4(0.f, 0.f, 0.f, 0.f);
    float4 vs1 = z, ve1 = z, vs2 = z, ve2 = z;
    if (eA >= sA) {
        vs1 = *(const float4*)&g_h[(brow + sA) * N_TOT + col];
        ve1 = *(const float4*)&g_h[(brow + eA) * N_TOT + col];
    }
    if (eB >= sB) {
        vs2 = *(const float4*)&g_h[(brow + sB) * N_TOT + col];
        ve2 = *(const float4*)&g_h[(brow + eB) * N_TOT + col];
    }
    float* o1 = out + (size_t)q * (2 * P_DIM);
    float* o2 = out + ((size_t)NQ_DIM + q) * (2 * P_DIM);
    *(float4*)(o1 + col)          = vs1;
    *(float4*)(o1 + P_DIM + col)  = ve1;
    *(float4*)(o2 + col)          = vs2;
    *(float4*)(o2 + P_DIM + col)  = ve2;
}

// ---------------------------------------------------------------------------
// Inputs: flag, encoded_input, start_ids_1, end_ids_1, query_batch_idx,
// start_ids_2, end_ids_2, W, b. Output: res1 then res2, each [NQ, 512] fp32.
// ---------------------------------------------------------------------------
extern "C" void kernel_launch(void* const* d_in, const int* in_sizes, int n_in,
                              void* d_out, int out_size) {
    const float* enc  = (const float*)d_in[1];
    const int*   s1   = (const int*)d_in[2];
    const int*   e1   = (const int*)d_in[3];
    const int*   qb   = (const int*)d_in[4];
    const int*   s2   = (const int*)d_in[5];
    const int*   e2   = (const int*)d_in[6];
    const float* W    = (const float*)d_in[7];
    const float* bias = (const float*)d_in[8];
    float* out = (float*)d_out;

    cudaFuncSetAttribute(gemm_fused_kernel,
                         cudaFuncAttributeMaxDynamicSharedMemorySize, SMEM_GEMM);

    split_w_kernel<<<K_TOT / 4, 256>>>(W);                       // 256 blocks
    gemm_fused_kernel<<<M_TOT / BM, NTHR, SMEM_GEMM>>>(enc, bias);
    gather_kernel<<<NQ_DIM / 4, 256>>>(qb, s1, e1, s2, e2, out);
}